// round 14
// baseline (speedup 1.0000x reference)
#include <cuda_runtime.h>
#include <cuda_fp16.h>
#include <math.h>

#define T_    256
#define B_    64
#define H_    1024
#define TBH   (T_*B_*H_)        // 16,777,216
#define K2    2048
#define N3    3072

// ---- persistent-kernel smem geometry ----
#define WROW   2056              // weight smem row stride in halfs (2048 + 8 pad)
#define NWSM   (48*WROW)         // 48 rows (3 gates x 16 cols), halfs
#define AROW   72                // A stage row stride in halfs (64 + 8 pad)
#define ASTG   (64*AROW)         // halfs per A stage (64 rows x 64 k-chunk)
#define SMEM_BYTES ((NWSM + 3*ASTG)*2)   // 225,024 bytes

// ---------------- static device scratch (allocation-free) ----------------
__device__ __half g_W[6u*N3*K2];          // [m][n][k] k-contig: k<1024 Wih, else Whh
__device__ float  g_bias[6][4][H_];       // [m][{r,z,in,hn}][j]
__device__ __half g_emb[TBH];             // relu(emb[tok])  (module 0 input)
__device__ __half g_seq[6][TBH];          // each module's output sequence (= h_t)
__device__ __half g_relu1[TBH];           // relu(enc1 out)  (module 2 input)
__device__ float  g_h32[6][B_*H_];        // fp32 recurrent state
__device__ __half g_zero[B_*H_];          // stays zero (zero-initialized)
__device__ unsigned g_bar_count;          // grid barrier arrival counter
__device__ unsigned g_bar_gen;            // grid barrier generation (monotonic)

// ---------------- mma helper ----------------
__device__ __forceinline__ void mma16816(float* c, const unsigned* a,
                                         unsigned b0, unsigned b1) {
    asm volatile(
        "mma.sync.aligned.m16n8k16.row.col.f32.f16.f16.f32 "
        "{%0,%1,%2,%3},{%4,%5,%6,%7},{%8,%9},{%0,%1,%2,%3};\n"
        : "+f"(c[0]), "+f"(c[1]), "+f"(c[2]), "+f"(c[3])
        : "r"(a[0]), "r"(a[1]), "r"(a[2]), "r"(a[3]), "r"(b0), "r"(b1));
}

// prefetch one A k-chunk (64 k) for all 64 batch rows into a stage (cp.async.cg: L2-only,
// coherent across the grid barrier). c in [0,32): c<16 -> x part, else h part.
__device__ __forceinline__ void prefA64(const __half* __restrict__ xsrc,
                                        const __half* __restrict__ hsrc,
                                        __half* stage, int c, int tid)
{
    const __half* base = (c < 16) ? (xsrc + (c << 6)) : (hsrc + ((c - 16) << 6));
#pragma unroll
    for (int i = 0; i < 4; i++) {
        int idx = tid + i * 128;          // 0..511 : 64 rows x 8 16B-segments
        int row = idx >> 3, s = idx & 7;
        const __half* src = base + row * H_ + s * 8;
        unsigned d = (unsigned)__cvta_generic_to_shared(stage + row * AROW + s * 8);
        asm volatile("cp.async.cg.shared.global [%0], [%1], 16;\n" :: "r"(d), "l"(src));
    }
}

// mma work for one 64-k chunk. GN = accumulator set for the n-gate block (2=i_n, 3=h_n).
template <int GN>
__device__ __forceinline__ void chunk64(const __half* __restrict__ S,
                                        const __half* __restrict__ Wsm, int c,
                                        float (&acc)[4][2][4],
                                        int ms, int ns, int t4, int tm)
{
#pragma unroll
    for (int ks = 0; ks < 4; ks++) {
        const int kk = ks * 16 + tm * 2;
        unsigned a[2][4];
#pragma unroll
        for (int mt = 0; mt < 2; mt++) {
            const __half* p = S + (ms * 32 + mt * 16 + t4) * AROW + kk;
            a[mt][0] = *(const unsigned*)(p);
            a[mt][1] = *(const unsigned*)(p + 8 * AROW);
            a[mt][2] = *(const unsigned*)(p + 8);
            a[mt][3] = *(const unsigned*)(p + 8 * AROW + 8);
        }
#pragma unroll
        for (int q = 0; q < 3; q++) {
            const __half* p = Wsm + (q * 16 + ns * 8 + t4) * WROW + (c << 6) + kk;
            unsigned b0 = *(const unsigned*)(p);
            unsigned b1 = *(const unsigned*)(p + 8);
            const int gs = (q == 2) ? GN : q;
            mma16816(acc[gs][0], a[0], b0, b1);
            mma16816(acc[gs][1], a[1], b0, b1);
        }
    }
}

__device__ __forceinline__ float fast_sigmoid(float x) {
    return __fdividef(1.f, 1.f + __expf(-x));
}
__device__ __forceinline__ float fast_tanh(float x) {
    return 1.f - 2.f * __fdividef(1.f, __expf(2.f * x) + 1.f);
}

// ---------------- persistent kernel: all 770 waves, grid barrier between ----------------
// grid = 128 CTAs: blockIdx = slot*64 + jtile. CTA keeps its 192KB weight slice in smem
// for a whole segment; per wave it computes h_new[64 x 16] for its module-timestep.
__global__ void __launch_bounds__(128, 1) persist_kernel()
{
    extern __shared__ __half sm[];
    __half* Wsm = sm;                  // 48 x WROW
    __half* Asm = sm + NWSM;           // 3 stages of 64 x AROW

    const int tid  = threadIdx.x;
    const int slot = blockIdx.x >> 6;
    const int jt   = blockIdx.x & 63;
    const int lane = tid & 31, warp = tid >> 5;
    const int ms = warp & 1, ns = warp >> 1;
    const int t4 = lane >> 2, tm = lane & 3;

    // barrier generation base (survives graph replays: monotonic across launches)
    __shared__ unsigned s_gen0;
    if (tid == 0) s_gen0 = *(volatile unsigned*)&g_bar_gen;
    __syncthreads();
    unsigned bar_target = s_gen0;

    for (int seg = 0; seg < 3; seg++) {
        const int m = seg * 2 + slot;

        // ---- load this segment's weight slice into smem (once per 256 timesteps) ----
        {
            const __half* Wm = g_W + (size_t)m * N3 * K2;
            for (int i = tid; i < 48 * 256; i += 128) {
                int r = i >> 8, s = i & 255;   // r: gate-row 0..47, s: 16B segment along k
                const __half* src = Wm
                    + (size_t)((r >> 4) * H_ + jt * 16 + (r & 15)) * K2 + s * 8;
                unsigned d = (unsigned)__cvta_generic_to_shared(Wsm + r * WROW + s * 8);
                asm volatile("cp.async.cg.shared.global [%0], [%1], 16;\n"
                             :: "r"(d), "l"(src));
            }
            asm volatile("cp.async.commit_group;\ncp.async.wait_group 0;\n" ::: "memory");
            __syncthreads();
        }

        const int nwl = (seg < 2) ? 257 : 256;
        for (int wl = 0; wl < nwl; wl++) {
            const int t = wl - ((seg < 2) ? slot : 0);

            if (t >= 0 && t < 256) {
                const __half* xsrc =
                    (m == 0) ? g_emb : (m == 1) ? g_seq[0] : (m == 2) ? g_relu1
                             : (m == 3) ? g_seq[2] : g_seq[3];
                xsrc += (size_t)t << 16;
                const __half* hsrc = (t == 0)
                    ? ((m < 2) ? g_zero : g_seq[m - 2] + ((size_t)255 << 16))
                    : (g_seq[m] + ((size_t)(t - 1) << 16));

                prefA64(xsrc, hsrc, Asm + 0 * ASTG, 0, tid);
                asm volatile("cp.async.commit_group;\n");
                prefA64(xsrc, hsrc, Asm + 1 * ASTG, 1, tid);
                asm volatile("cp.async.commit_group;\n");
                prefA64(xsrc, hsrc, Asm + 2 * ASTG, 2, tid);
                asm volatile("cp.async.commit_group;\n");

                float acc[4][2][4];
#pragma unroll
                for (int g = 0; g < 4; g++)
#pragma unroll
                    for (int mt = 0; mt < 2; mt++)
#pragma unroll
                        for (int e = 0; e < 4; e++) acc[g][mt][e] = 0.f;

                for (int c = 0; c < 32; c++) {
                    asm volatile("cp.async.wait_group 2;\n" ::: "memory");
                    __syncthreads();
                    const __half* S = Asm + (c % 3) * ASTG;
                    if (c < 16) chunk64<2>(S, Wsm, c, acc, ms, ns, t4, tm);
                    else        chunk64<3>(S, Wsm, c, acc, ms, ns, t4, tm);
                    __syncthreads();
                    if (c + 3 < 32)
                        prefA64(xsrc, hsrc, Asm + (c % 3) * ASTG, c + 3, tid);
                    asm volatile("cp.async.commit_group;\n");
                }

                // ---- fused GRU gate epilogue ----
                const float* bias = &g_bias[m][0][0];
                float*       h32  = &g_h32[m][0];
                __half*      outp = g_seq[m] + ((size_t)t << 16);

#pragma unroll
                for (int mt = 0; mt < 2; mt++) {
#pragma unroll
                    for (int e = 0; e < 4; e++) {
                        const int row = ms * 32 + mt * 16 + t4 + ((e >> 1) << 3);
                        const int col = jt * 16 + ns * 8 + tm * 2 + (e & 1);
                        const int off = row * H_ + col;
                        float r  = fast_sigmoid(acc[0][mt][e] + bias[col]);
                        float z  = fast_sigmoid(acc[1][mt][e] + bias[H_ + col]);
                        float nn = fast_tanh(acc[2][mt][e] + bias[2 * H_ + col]
                                             + r * (acc[3][mt][e] + bias[3 * H_ + col]));
                        float hp = (t == 0) ? ((m < 2) ? 0.f : g_h32[m - 2][off])
                                            : h32[off];
                        float hv = (1.f - z) * nn + z * hp;
                        h32[off]  = hv;
                        outp[off] = __float2half(hv);
                        if (m == 1)
                            g_relu1[((size_t)t << 16) + off] =
                                __float2half(fmaxf(hv, 0.f));
                    }
                }
            }

            // ---- grid barrier between waves ----
            bar_target++;
            __threadfence();        // flush this thread's stores to device scope
            __syncthreads();        // all warps' stores done + fenced before arrive
            if (tid == 0) {
                unsigned arr = atomicAdd(&g_bar_count, 1);
                if (arr == 127) {
                    atomicExch(&g_bar_count, 0);
                    __threadfence();
                    atomicExch(&g_bar_gen, bar_target);
                } else {
                    while (*(volatile unsigned*)&g_bar_gen < bar_target) { }
                }
            }
            __syncthreads();
        }
    }
}

// ---------------- preprocessing kernels ----------------
__global__ void convert_w_kernel(const float* __restrict__ eWih, const float* __restrict__ eWhh,
                                 const float* __restrict__ gWih, const float* __restrict__ gWhh,
                                 const float* __restrict__ cWih, const float* __restrict__ cWhh)
{
    unsigned idx = blockIdx.x * 256u + threadIdx.x;
    if (idx >= 6u * N3 * K2) return;
    int m = idx / (N3 * K2);
    int rem = idx % (N3 * K2);
    int n = rem / K2, k = rem % K2;
    const float *ih, *hh;
    if (m < 2)      { ih = eWih; hh = eWhh; }
    else if (m < 4) { ih = gWih; hh = gWhh; }
    else            { ih = cWih; hh = cWhh; }
    int l = m & 1;
    float v = (k < H_) ? ih[(size_t)(l * N3 + n) * H_ + k]
                       : hh[(size_t)(l * N3 + n) * H_ + (k - H_)];
    g_W[idx] = __float2half(v);
}

__global__ void convert_b_kernel(const float* __restrict__ ebih, const float* __restrict__ ebhh,
                                 const float* __restrict__ gbih, const float* __restrict__ gbhh,
                                 const float* __restrict__ cbih, const float* __restrict__ cbhh)
{
    int idx = blockIdx.x * 256 + threadIdx.x;
    if (idx >= 6 * H_) return;
    int m = idx / H_, j = idx % H_;
    const float *bih, *bhh;
    if (m < 2)      { bih = ebih; bhh = ebhh; }
    else if (m < 4) { bih = gbih; bhh = gbhh; }
    else            { bih = cbih; bhh = cbhh; }
    int l = m & 1;
    bih += l * N3; bhh += l * N3;
    g_bias[m][0][j] = bih[j]          + bhh[j];           // r (combined)
    g_bias[m][1][j] = bih[H_ + j]     + bhh[H_ + j];      // z (combined)
    g_bias[m][2][j] = bih[2 * H_ + j];                     // i_n
    g_bias[m][3][j] = bhh[2 * H_ + j];                     // h_n
}

__global__ void embed_kernel(const int* __restrict__ input, const float* __restrict__ emb)
{
    unsigned idx = blockIdx.x * 256u + threadIdx.x;  // over T*B*H
    if (idx >= (unsigned)TBH) return;
    int i = idx >> 10, k = idx & 1023;
    int tok = input[i]; if (tok < 0) tok = 0;
    g_emb[idx] = __float2half(fmaxf(emb[(size_t)tok * H_ + k], 0.f));
}

__global__ void score_kernel(const float* __restrict__ W, const float* __restrict__ b,
                             float* __restrict__ out)
{
    int row  = blockIdx.x * 4 + (threadIdx.x >> 5);   // 0..16383 (= t*64+b)
    int lane = threadIdx.x & 31;
    const __half* c0 = g_seq[4] + (size_t)row * H_;
    const __half* c1 = g_seq[5] + (size_t)row * H_;
    float s = 0.f;
    for (int j = lane; j < H_; j += 32)
        s += __half2float(c0[j]) * W[j] + __half2float(c1[j]) * W[H_ + j];
#pragma unroll
    for (int o = 16; o; o >>= 1) s += __shfl_xor_sync(0xffffffffu, s, o);
    if (lane == 0) out[row] = 1.f / (1.f + expf(-(s + b[0])));
}

// ---------------- launch ----------------
extern "C" void kernel_launch(void* const* d_in, const int* in_sizes, int n_in,
                              void* d_out, int out_size)
{
    const int*   input = (const int*)  d_in[0];
    const float* emb   = (const float*)d_in[1];
    const float* eWih  = (const float*)d_in[2];
    const float* eWhh  = (const float*)d_in[3];
    const float* ebih  = (const float*)d_in[4];
    const float* ebhh  = (const float*)d_in[5];
    const float* gWih  = (const float*)d_in[6];
    const float* gWhh  = (const float*)d_in[7];
    const float* gbih  = (const float*)d_in[8];
    const float* gbhh  = (const float*)d_in[9];
    const float* cWih  = (const float*)d_in[10];
    const float* cWhh  = (const float*)d_in[11];
    const float* cbih  = (const float*)d_in[12];
    const float* cbhh  = (const float*)d_in[13];
    const float* sW    = (const float*)d_in[14];
    const float* sb    = (const float*)d_in[15];

    static bool attr_done = false;
    if (!attr_done) {
        cudaFuncSetAttribute(persist_kernel,
                             cudaFuncAttributeMaxDynamicSharedMemorySize, SMEM_BYTES);
        attr_done = true;
    }

    convert_w_kernel<<<(6u * N3 * K2 + 255) / 256, 256>>>(eWih, eWhh, gWih, gWhh, cWih, cWhh);
    convert_b_kernel<<<24, 256>>>(ebih, ebhh, gbih, gbhh, cbih, cbhh);
    embed_kernel<<<(TBH + 255) / 256, 256>>>(input, emb);

    persist_kernel<<<128, 128, SMEM_BYTES>>>();

    score_kernel<<<T_ * B_ / 4, 128>>>(sW, sb, (float*)d_out);
}

// round 15
// speedup vs baseline: 1.0551x; 1.0551x over previous
#include <cuda_runtime.h>
#include <cuda_fp16.h>
#include <math.h>

#define T_    256
#define B_    64
#define H_    1024
#define TBH   (T_*B_*H_)        // 16,777,216
#define K2    2048
#define N3    3072

// ---- persistent-kernel smem geometry ----
#define WROW   2056              // weight smem row stride in halfs (2048 + 8 pad)
#define NWSM   (48*WROW)         // 48 rows (3 gates x 16 cols), halfs
#define AROW   72                // A stage row stride in halfs (64 + 8 pad)
#define ASTG   (64*AROW)         // halfs per A stage (64 rows x 64 k-chunk)
#define SMEM_BYTES ((NWSM + 3*ASTG)*2)   // 225,024 bytes

// ---------------- static device scratch (allocation-free) ----------------
__device__ __half g_W[6u*N3*K2];          // [m][n][k] k-contig: k<1024 Wih, else Whh
__device__ float  g_bias[6][4][H_];       // [m][{r,z,in,hn}][j]
__device__ __half g_emb[TBH];             // relu(emb[tok])  (module 0 input)
__device__ __half g_seq[6][TBH];          // each module's output sequence (= h_t)
__device__ __half g_relu1[TBH];           // relu(enc1 out)  (module 2 input)
__device__ float  g_h32[6][B_*H_];        // fp32 recurrent state
__device__ __half g_zero[B_*H_];          // stays zero (zero-initialized)
__device__ unsigned g_bar_count;          // grid barrier arrival counter
__device__ unsigned g_bar_gen;            // grid barrier generation (monotonic)

// ---------------- mma helper ----------------
__device__ __forceinline__ void mma16816(float* c, const unsigned* a,
                                         unsigned b0, unsigned b1) {
    asm volatile(
        "mma.sync.aligned.m16n8k16.row.col.f32.f16.f16.f32 "
        "{%0,%1,%2,%3},{%4,%5,%6,%7},{%8,%9},{%0,%1,%2,%3};\n"
        : "+f"(c[0]), "+f"(c[1]), "+f"(c[2]), "+f"(c[3])
        : "r"(a[0]), "r"(a[1]), "r"(a[2]), "r"(a[3]), "r"(b0), "r"(b1));
}

// prefetch one A k-chunk (64 k) for all 64 batch rows into a stage (cp.async.cg: L2-only,
// coherent across the grid barrier). c in [0,32): c<16 -> x part, else h part.
__device__ __forceinline__ void prefA64(const __half* __restrict__ xsrc,
                                        const __half* __restrict__ hsrc,
                                        __half* stage, int c, int tid)
{
    const __half* base = (c < 16) ? (xsrc + (c << 6)) : (hsrc + ((c - 16) << 6));
#pragma unroll
    for (int i = 0; i < 4; i++) {
        int idx = tid + i * 128;          // 0..511 : 64 rows x 8 16B-segments
        int row = idx >> 3, s = idx & 7;
        const __half* src = base + row * H_ + s * 8;
        unsigned d = (unsigned)__cvta_generic_to_shared(stage + row * AROW + s * 8);
        asm volatile("cp.async.cg.shared.global [%0], [%1], 16;\n" :: "r"(d), "l"(src));
    }
}

// mma work for one 64-k chunk. GN = accumulator set for the n-gate block (2=i_n, 3=h_n).
template <int GN>
__device__ __forceinline__ void chunk64(const __half* __restrict__ S,
                                        const __half* __restrict__ Wsm, int c,
                                        float (&acc)[4][2][4],
                                        int ms, int ns, int t4, int tm)
{
#pragma unroll
    for (int ks = 0; ks < 4; ks++) {
        const int kk = ks * 16 + tm * 2;
        unsigned a[2][4];
#pragma unroll
        for (int mt = 0; mt < 2; mt++) {
            const __half* p = S + (ms * 32 + mt * 16 + t4) * AROW + kk;
            a[mt][0] = *(const unsigned*)(p);
            a[mt][1] = *(const unsigned*)(p + 8 * AROW);
            a[mt][2] = *(const unsigned*)(p + 8);
            a[mt][3] = *(const unsigned*)(p + 8 * AROW + 8);
        }
#pragma unroll
        for (int q = 0; q < 3; q++) {
            const __half* p = Wsm + (q * 16 + ns * 8 + t4) * WROW + (c << 6) + kk;
            unsigned b0 = *(const unsigned*)(p);
            unsigned b1 = *(const unsigned*)(p + 8);
            const int gs = (q == 2) ? GN : q;
            mma16816(acc[gs][0], a[0], b0, b1);
            mma16816(acc[gs][1], a[1], b0, b1);
        }
    }
}

__device__ __forceinline__ float fast_sigmoid(float x) {
    return __fdividef(1.f, 1.f + __expf(-x));
}
__device__ __forceinline__ float fast_tanh(float x) {
    return 1.f - 2.f * __fdividef(1.f, __expf(2.f * x) + 1.f);
}

// ---------------- persistent kernel: all 770 waves, grid barrier between ----------------
// grid = 128 CTAs: blockIdx = slot*64 + jtile. CTA keeps its 192KB weight slice in smem
// for a whole segment; per wave it computes h_new[64 x 16] for its module-timestep.
__global__ void __launch_bounds__(128, 1) persist_kernel()
{
    extern __shared__ __half sm[];
    __half* Wsm = sm;                  // 48 x WROW
    __half* Asm = sm + NWSM;           // 3 stages of 64 x AROW

    const int tid  = threadIdx.x;
    const int slot = blockIdx.x >> 6;
    const int jt   = blockIdx.x & 63;
    const int lane = tid & 31, warp = tid >> 5;
    const int ms = warp & 1, ns = warp >> 1;
    const int t4 = lane >> 2, tm = lane & 3;

    // barrier generation base (survives graph replays: monotonic across launches)
    __shared__ unsigned s_gen0;
    if (tid == 0) s_gen0 = *(volatile unsigned*)&g_bar_gen;
    __syncthreads();
    unsigned bar_target = s_gen0;

    for (int seg = 0; seg < 3; seg++) {
        const int m = seg * 2 + slot;

        // ---- load this segment's weight slice into smem (once per 256 timesteps) ----
        {
            const __half* Wm = g_W + (size_t)m * N3 * K2;
            for (int i = tid; i < 48 * 256; i += 128) {
                int r = i >> 8, s = i & 255;   // r: gate-row 0..47, s: 16B segment along k
                const __half* src = Wm
                    + (size_t)((r >> 4) * H_ + jt * 16 + (r & 15)) * K2 + s * 8;
                unsigned d = (unsigned)__cvta_generic_to_shared(Wsm + r * WROW + s * 8);
                asm volatile("cp.async.cg.shared.global [%0], [%1], 16;\n"
                             :: "r"(d), "l"(src));
            }
            asm volatile("cp.async.commit_group;\ncp.async.wait_group 0;\n" ::: "memory");
            __syncthreads();
        }

        const int nwl = (seg < 2) ? 257 : 256;
        for (int wl = 0; wl < nwl; wl++) {
            const int t = wl - ((seg < 2) ? slot : 0);

            if (t >= 0 && t < 256) {
                const __half* xsrc =
                    (m == 0) ? g_emb : (m == 1) ? g_seq[0] : (m == 2) ? g_relu1
                             : (m == 3) ? g_seq[2] : g_seq[3];
                xsrc += (size_t)t << 16;
                const __half* hsrc = (t == 0)
                    ? ((m < 2) ? g_zero : g_seq[m - 2] + ((size_t)255 << 16))
                    : (g_seq[m] + ((size_t)(t - 1) << 16));

                prefA64(xsrc, hsrc, Asm + 0 * ASTG, 0, tid);
                asm volatile("cp.async.commit_group;\n");
                prefA64(xsrc, hsrc, Asm + 1 * ASTG, 1, tid);
                asm volatile("cp.async.commit_group;\n");
                prefA64(xsrc, hsrc, Asm + 2 * ASTG, 2, tid);
                asm volatile("cp.async.commit_group;\n");

                float acc[4][2][4];
#pragma unroll
                for (int g = 0; g < 4; g++)
#pragma unroll
                    for (int mt = 0; mt < 2; mt++)
#pragma unroll
                        for (int e = 0; e < 4; e++) acc[g][mt][e] = 0.f;

                for (int c = 0; c < 32; c++) {
                    asm volatile("cp.async.wait_group 2;\n" ::: "memory");
                    __syncthreads();
                    const __half* S = Asm + (c % 3) * ASTG;
                    if (c < 16) chunk64<2>(S, Wsm, c, acc, ms, ns, t4, tm);
                    else        chunk64<3>(S, Wsm, c, acc, ms, ns, t4, tm);
                    __syncthreads();
                    if (c + 3 < 32)
                        prefA64(xsrc, hsrc, Asm + (c % 3) * ASTG, c + 3, tid);
                    asm volatile("cp.async.commit_group;\n");
                }

                // ---- fused GRU gate epilogue ----
                const float* bias = &g_bias[m][0][0];
                float*       h32  = &g_h32[m][0];
                __half*      outp = g_seq[m] + ((size_t)t << 16);

#pragma unroll
                for (int mt = 0; mt < 2; mt++) {
#pragma unroll
                    for (int e = 0; e < 4; e++) {
                        const int row = ms * 32 + mt * 16 + t4 + ((e >> 1) << 3);
                        const int col = jt * 16 + ns * 8 + tm * 2 + (e & 1);
                        const int off = row * H_ + col;
                        float r  = fast_sigmoid(acc[0][mt][e] + bias[col]);
                        float z  = fast_sigmoid(acc[1][mt][e] + bias[H_ + col]);
                        float nn = fast_tanh(acc[2][mt][e] + bias[2 * H_ + col]
                                             + r * (acc[3][mt][e] + bias[3 * H_ + col]));
                        float hp = (t == 0) ? ((m < 2) ? 0.f : g_h32[m - 2][off])
                                            : h32[off];
                        float hv = (1.f - z) * nn + z * hp;
                        h32[off]  = hv;
                        outp[off] = __float2half(hv);
                        if (m == 1)
                            g_relu1[((size_t)t << 16) + off] =
                                __float2half(fmaxf(hv, 0.f));
                    }
                }
            }

            // ---- grid barrier between waves ----
            bar_target++;
            __threadfence();        // flush this thread's stores to device scope
            __syncthreads();        // all warps' stores done + fenced before arrive
            if (tid == 0) {
                unsigned arr = atomicAdd(&g_bar_count, 1);
                if (arr == 127) {
                    atomicExch(&g_bar_count, 0);
                    __threadfence();
                    atomicExch(&g_bar_gen, bar_target);
                } else {
                    while (*(volatile unsigned*)&g_bar_gen < bar_target) { }
                }
            }
            __syncthreads();
        }
    }
}

// ---------------- preprocessing kernels ----------------
__global__ void convert_w_kernel(const float* __restrict__ eWih, const float* __restrict__ eWhh,
                                 const float* __restrict__ gWih, const float* __restrict__ gWhh,
                                 const float* __restrict__ cWih, const float* __restrict__ cWhh)
{
    unsigned idx = blockIdx.x * 256u + threadIdx.x;
    if (idx >= 6u * N3 * K2) return;
    int m = idx / (N3 * K2);
    int rem = idx % (N3 * K2);
    int n = rem / K2, k = rem % K2;
    const float *ih, *hh;
    if (m < 2)      { ih = eWih; hh = eWhh; }
    else if (m < 4) { ih = gWih; hh = gWhh; }
    else            { ih = cWih; hh = cWhh; }
    int l = m & 1;
    float v = (k < H_) ? ih[(size_t)(l * N3 + n) * H_ + k]
                       : hh[(size_t)(l * N3 + n) * H_ + (k - H_)];
    g_W[idx] = __float2half(v);
}

__global__ void convert_b_kernel(const float* __restrict__ ebih, const float* __restrict__ ebhh,
                                 const float* __restrict__ gbih, const float* __restrict__ gbhh,
                                 const float* __restrict__ cbih, const float* __restrict__ cbhh)
{
    int idx = blockIdx.x * 256 + threadIdx.x;
    if (idx >= 6 * H_) return;
    int m = idx / H_, j = idx % H_;
    const float *bih, *bhh;
    if (m < 2)      { bih = ebih; bhh = ebhh; }
    else if (m < 4) { bih = gbih; bhh = gbhh; }
    else            { bih = cbih; bhh = cbhh; }
    int l = m & 1;
    bih += l * N3; bhh += l * N3;
    g_bias[m][0][j] = bih[j]          + bhh[j];           // r (combined)
    g_bias[m][1][j] = bih[H_ + j]     + bhh[H_ + j];      // z (combined)
    g_bias[m][2][j] = bih[2 * H_ + j];                     // i_n
    g_bias[m][3][j] = bhh[2 * H_ + j];                     // h_n
}

__global__ void embed_kernel(const int* __restrict__ input, const float* __restrict__ emb)
{
    unsigned idx = blockIdx.x * 256u + threadIdx.x;  // over T*B*H
    if (idx >= (unsigned)TBH) return;
    int i = idx >> 10, k = idx & 1023;
    int tok = input[i]; if (tok < 0) tok = 0;
    g_emb[idx] = __float2half(fmaxf(emb[(size_t)tok * H_ + k], 0.f));
}

__global__ void score_kernel(const float* __restrict__ W, const float* __restrict__ b,
                             float* __restrict__ out)
{
    int row  = blockIdx.x * 4 + (threadIdx.x >> 5);   // 0..16383 (= t*64+b)
    int lane = threadIdx.x & 31;
    const __half* c0 = g_seq[4] + (size_t)row * H_;
    const __half* c1 = g_seq[5] + (size_t)row * H_;
    float s = 0.f;
    for (int j = lane; j < H_; j += 32)
        s += __half2float(c0[j]) * W[j] + __half2float(c1[j]) * W[H_ + j];
#pragma unroll
    for (int o = 16; o; o >>= 1) s += __shfl_xor_sync(0xffffffffu, s, o);
    if (lane == 0) out[row] = 1.f / (1.f + expf(-(s + b[0])));
}

// ---------------- launch ----------------
extern "C" void kernel_launch(void* const* d_in, const int* in_sizes, int n_in,
                              void* d_out, int out_size)
{
    const int*   input = (const int*)  d_in[0];
    const float* emb   = (const float*)d_in[1];
    const float* eWih  = (const float*)d_in[2];
    const float* eWhh  = (const float*)d_in[3];
    const float* ebih  = (const float*)d_in[4];
    const float* ebhh  = (const float*)d_in[5];
    const float* gWih  = (const float*)d_in[6];
    const float* gWhh  = (const float*)d_in[7];
    const float* gbih  = (const float*)d_in[8];
    const float* gbhh  = (const float*)d_in[9];
    const float* cWih  = (const float*)d_in[10];
    const float* cWhh  = (const float*)d_in[11];
    const float* cbih  = (const float*)d_in[12];
    const float* cbhh  = (const float*)d_in[13];
    const float* sW    = (const float*)d_in[14];
    const float* sb    = (const float*)d_in[15];

    static bool attr_done = false;
    if (!attr_done) {
        cudaFuncSetAttribute(persist_kernel,
                             cudaFuncAttributeMaxDynamicSharedMemorySize, SMEM_BYTES);
        attr_done = true;
    }

    convert_w_kernel<<<(6u * N3 * K2 + 255) / 256, 256>>>(eWih, eWhh, gWih, gWhh, cWih, cWhh);
    convert_b_kernel<<<24, 256>>>(ebih, ebhh, gbih, gbhh, cbih, cbhh);
    embed_kernel<<<(TBH + 255) / 256, 256>>>(input, emb);

    persist_kernel<<<128, 128, SMEM_BYTES>>>();

    score_kernel<<<T_ * B_ / 4, 128>>>(sW, sb, (float*)d_out);
}